// round 1
// baseline (speedup 1.0000x reference)
#include <cuda_runtime.h>
#include <cuda_bf16.h>
#include <math.h>

// Problem dims
#define MDIM   8192      // B*S
#define DMODEL 768
#define DFF    2048
#define SEQ    2048
#define BATCH  4
#define NHEAD  12
#define DK     64

// ---------------- scratch (device globals; no allocations allowed) -------------
__device__ float g_Q[MDIM * DMODEL];
__device__ float g_K[MDIM * DMODEL];
__device__ float g_V[MDIM * DMODEL];
__device__ float g_attn[MDIM * DMODEL];
__device__ float g_res1[MDIM * DMODEL];
__device__ float g_x1[MDIM * DMODEL];
__device__ float g_h[MDIM * DFF];
__device__ float g_res2[MDIM * DMODEL];

// ---------------- SGEMM: C = A[M,K] @ B[K,N] + bias (+resid) (+relu) ----------
// 128x128 block tile, BK=16, 256 threads, 8x8 per-thread micro-tile.
template<int DO_RELU, int DO_RES>
__global__ __launch_bounds__(256, 2)
void sgemm_kernel(const float* __restrict__ A, const float* __restrict__ Bm,
                  const float* __restrict__ bias, const float* __restrict__ resid,
                  float* __restrict__ C, int M, int N, int K)
{
    __shared__ float As[16][128];
    __shared__ float Bs[16][128];

    const int tid = threadIdx.x;
    const int tx = tid & 15;        // 0..15 (col group)
    const int ty = tid >> 4;        // 0..15 (row group)
    const int row0 = blockIdx.y * 128;
    const int col0 = blockIdx.x * 128;

    float acc[8][8];
#pragma unroll
    for (int i = 0; i < 8; i++)
#pragma unroll
        for (int j = 0; j < 8; j++) acc[i][j] = 0.0f;

    for (int k0 = 0; k0 < K; k0 += 16) {
        // load A tile (128 rows x 16 cols) -> As[k][m]
#pragma unroll
        for (int i = 0; i < 2; i++) {
            int f = tid * 2 + i;            // 0..511
            int r = f >> 2;                 // 0..127
            int seg = f & 3;                // 0..3
            float4 v = *(const float4*)&A[(size_t)(row0 + r) * K + k0 + seg * 4];
            As[seg * 4 + 0][r] = v.x;
            As[seg * 4 + 1][r] = v.y;
            As[seg * 4 + 2][r] = v.z;
            As[seg * 4 + 3][r] = v.w;
        }
        // load B tile (16 rows x 128 cols) -> Bs[k][n]
#pragma unroll
        for (int i = 0; i < 2; i++) {
            int f = tid * 2 + i;            // 0..511
            int r = f >> 5;                 // 0..15
            int c4 = f & 31;                // 0..31
            *(float4*)&Bs[r][c4 * 4] =
                *(const float4*)&Bm[(size_t)(k0 + r) * N + col0 + c4 * 4];
        }
        __syncthreads();

#pragma unroll
        for (int kk = 0; kk < 16; kk++) {
            float a[8], b[8];
            *(float4*)&a[0] = *(float4*)&As[kk][ty * 8];
            *(float4*)&a[4] = *(float4*)&As[kk][ty * 8 + 4];
            *(float4*)&b[0] = *(float4*)&Bs[kk][tx * 8];
            *(float4*)&b[4] = *(float4*)&Bs[kk][tx * 8 + 4];
#pragma unroll
            for (int i = 0; i < 8; i++)
#pragma unroll
                for (int j = 0; j < 8; j++)
                    acc[i][j] = fmaf(a[i], b[j], acc[i][j]);
        }
        __syncthreads();
    }

    // epilogue
    float bvals[8];
    {
        float4 b0 = *(const float4*)&bias[col0 + tx * 8];
        float4 b1 = *(const float4*)&bias[col0 + tx * 8 + 4];
        bvals[0] = b0.x; bvals[1] = b0.y; bvals[2] = b0.z; bvals[3] = b0.w;
        bvals[4] = b1.x; bvals[5] = b1.y; bvals[6] = b1.z; bvals[7] = b1.w;
    }
#pragma unroll
    for (int i = 0; i < 8; i++) {
        int r = row0 + ty * 8 + i;
        size_t base = (size_t)r * N + col0 + tx * 8;
        float v[8];
#pragma unroll
        for (int j = 0; j < 8; j++) v[j] = acc[i][j] + bvals[j];
        if (DO_RES) {
            float4 r0 = *(const float4*)&resid[base];
            float4 r1 = *(const float4*)&resid[base + 4];
            v[0] += r0.x; v[1] += r0.y; v[2] += r0.z; v[3] += r0.w;
            v[4] += r1.x; v[5] += r1.y; v[6] += r1.z; v[7] += r1.w;
        }
        if (DO_RELU) {
#pragma unroll
            for (int j = 0; j < 8; j++) v[j] = fmaxf(v[j], 0.0f);
        }
        float4 o0 = make_float4(v[0], v[1], v[2], v[3]);
        float4 o1 = make_float4(v[4], v[5], v[6], v[7]);
        *(float4*)&C[base] = o0;
        *(float4*)&C[base + 4] = o1;
    }
}

// ---------------- fused flash attention (fp32) --------------------------------
// grid: (SEQ/64, BATCH*NHEAD), block 256 (8 warps). Each warp owns 8 query rows.
// K-tile = 32 keys per iteration, online softmax.
__global__ __launch_bounds__(256)
void attention_kernel(const float* __restrict__ Q, const float* __restrict__ K,
                      const float* __restrict__ V, const float* __restrict__ mask,
                      float* __restrict__ Oout)
{
    __shared__ float Qs[64][65];
    __shared__ float Ks[32][65];
    __shared__ float Vs[32][65];
    __shared__ float Ps[64][48];
    __shared__ float Ms[32];

    const int tid = threadIdx.x;
    const int lane = tid & 31;
    const int w = tid >> 5;
    const int bh = blockIdx.y;
    const int b = bh / NHEAD;
    const int h = bh % NHEAD;
    const int q0 = blockIdx.x * 64;
    const float scale = 0.125f; // 1/sqrt(64)

    // load Q tile [64 x 64]
    for (int idx = tid; idx < 64 * 64; idx += 256) {
        int r = idx >> 6, d = idx & 63;
        Qs[r][d] = Q[(size_t)(b * SEQ + q0 + r) * DMODEL + h * DK + d];
    }

    float m_[8], l_[8], o0[8], o1[8];
#pragma unroll
    for (int i = 0; i < 8; i++) { m_[i] = -1e30f; l_[i] = 0.0f; o0[i] = 0.0f; o1[i] = 0.0f; }

    const int rbase = w * 8 + (lane >> 4);   // this lane's first row (then +2,+4,+6)
    const int cbase = lane & 15;             // cols cbase, cbase+16

    __syncthreads();

    for (int kt = 0; kt < SEQ / 32; kt++) {
        const int k0 = kt * 32;
        __syncthreads();   // previous PV done before overwriting Ks/Vs
        for (int idx = tid; idx < 32 * 64; idx += 256) {
            int r = idx >> 6, d = idx & 63;
            size_t g = (size_t)(b * SEQ + k0 + r) * DMODEL + h * DK + d;
            Ks[r][d] = K[g];
            Vs[r][d] = V[g];
        }
        if (tid < 32) Ms[tid] = mask[b * SEQ + k0 + tid];
        __syncthreads();

        // S = Q K^T  (4 rows x 2 cols per lane)
        float s[4][2];
#pragma unroll
        for (int i = 0; i < 4; i++) { s[i][0] = 0.0f; s[i][1] = 0.0f; }
#pragma unroll
        for (int d = 0; d < 64; d++) {
            float kv0 = Ks[cbase][d];
            float kv1 = Ks[cbase + 16][d];
#pragma unroll
            for (int i = 0; i < 4; i++) {
                float q = Qs[rbase + 2 * i][d];
                s[i][0] = fmaf(q, kv0, s[i][0]);
                s[i][1] = fmaf(q, kv1, s[i][1]);
            }
        }
#pragma unroll
        for (int i = 0; i < 4; i++) {
            int r = rbase + 2 * i;
            Ps[r][cbase]      = fmaf(Ms[cbase],      -1e9f, s[i][0] * scale);
            Ps[r][cbase + 16] = fmaf(Ms[cbase + 16], -1e9f, s[i][1] * scale);
        }
        __syncwarp();

        // online softmax per row (warp handles its 8 rows)
#pragma unroll
        for (int rr = 0; rr < 8; rr++) {
            float sv = Ps[w * 8 + rr][lane];
            float tmax = sv;
#pragma unroll
            for (int off = 16; off > 0; off >>= 1)
                tmax = fmaxf(tmax, __shfl_xor_sync(0xffffffffu, tmax, off));
            float nm = fmaxf(m_[rr], tmax);
            float alpha = __expf(m_[rr] - nm);
            float p = __expf(sv - nm);
            float rs = p;
#pragma unroll
            for (int off = 16; off > 0; off >>= 1)
                rs += __shfl_xor_sync(0xffffffffu, rs, off);
            m_[rr] = nm;
            l_[rr] = l_[rr] * alpha + rs;
            o0[rr] *= alpha;
            o1[rr] *= alpha;
            Ps[w * 8 + rr][lane] = p;
        }
        __syncwarp();

        // O += P @ V
#pragma unroll
        for (int c = 0; c < 32; c++) {
            float v0 = Vs[c][lane];
            float v1 = Vs[c][lane + 32];
#pragma unroll
            for (int rr = 0; rr < 8; rr++) {
                float p = Ps[w * 8 + rr][c];
                o0[rr] = fmaf(p, v0, o0[rr]);
                o1[rr] = fmaf(p, v1, o1[rr]);
            }
        }
    }

    // write normalized output (head-concat layout [M, DMODEL])
#pragma unroll
    for (int rr = 0; rr < 8; rr++) {
        float inv = 1.0f / l_[rr];
        size_t base = (size_t)(b * SEQ + q0 + w * 8 + rr) * DMODEL + h * DK;
        Oout[base + lane]      = o0[rr] * inv;
        Oout[base + lane + 32] = o1[rr] * inv;
    }
}

// ---------------- LayerNorm over last dim (768) --------------------------------
__global__ __launch_bounds__(256)
void layernorm_kernel(const float* __restrict__ X, const float* __restrict__ gamma,
                      const float* __restrict__ beta, float* __restrict__ Y)
{
    const int row = blockIdx.x;
    const int tid = threadIdx.x;
    const float* x = X + (size_t)row * DMODEL;

    float v[3];
    float sum = 0.0f, sq = 0.0f;
#pragma unroll
    for (int i = 0; i < 3; i++) {
        v[i] = x[tid + i * 256];
        sum += v[i];
        sq = fmaf(v[i], v[i], sq);
    }
    // warp reduce
#pragma unroll
    for (int off = 16; off > 0; off >>= 1) {
        sum += __shfl_xor_sync(0xffffffffu, sum, off);
        sq  += __shfl_xor_sync(0xffffffffu, sq,  off);
    }
    __shared__ float rs[8], rq[8], bc[2];
    int w = tid >> 5, lane = tid & 31;
    if (lane == 0) { rs[w] = sum; rq[w] = sq; }
    __syncthreads();
    if (tid == 0) {
        float s = 0.0f, q = 0.0f;
#pragma unroll
        for (int i = 0; i < 8; i++) { s += rs[i]; q += rq[i]; }
        float mean = s * (1.0f / DMODEL);
        float var = q * (1.0f / DMODEL) - mean * mean;
        bc[0] = mean;
        bc[1] = rsqrtf(var + 1e-3f);
    }
    __syncthreads();
    float mean = bc[0], inv = bc[1];
#pragma unroll
    for (int i = 0; i < 3; i++) {
        int col = tid + i * 256;
        Y[(size_t)row * DMODEL + col] =
            (v[i] - mean) * inv * gamma[col] + beta[col];
    }
}

// ---------------- launch ---------------------------------------------------------
extern "C" void kernel_launch(void* const* d_in, const int* in_sizes, int n_in,
                              void* d_out, int out_size)
{
    const float* x    = (const float*)d_in[0];
    const float* mask = (const float*)d_in[1];
    const float* Wq   = (const float*)d_in[2];
    const float* bq   = (const float*)d_in[3];
    const float* Wk   = (const float*)d_in[4];
    const float* bk   = (const float*)d_in[5];
    const float* Wv   = (const float*)d_in[6];
    const float* bv   = (const float*)d_in[7];
    const float* Wo   = (const float*)d_in[8];
    const float* bo   = (const float*)d_in[9];
    const float* W1   = (const float*)d_in[10];
    const float* b1   = (const float*)d_in[11];
    const float* W2   = (const float*)d_in[12];
    const float* b2   = (const float*)d_in[13];
    const float* g1   = (const float*)d_in[14];
    const float* be1  = (const float*)d_in[15];
    const float* g2   = (const float*)d_in[16];
    const float* be2  = (const float*)d_in[17];

    float *pQ, *pK, *pV, *pAttn, *pRes1, *pX1, *pH, *pRes2;
    cudaGetSymbolAddress((void**)&pQ,    g_Q);
    cudaGetSymbolAddress((void**)&pK,    g_K);
    cudaGetSymbolAddress((void**)&pV,    g_V);
    cudaGetSymbolAddress((void**)&pAttn, g_attn);
    cudaGetSymbolAddress((void**)&pRes1, g_res1);
    cudaGetSymbolAddress((void**)&pX1,   g_x1);
    cudaGetSymbolAddress((void**)&pH,    g_h);
    cudaGetSymbolAddress((void**)&pRes2, g_res2);

    dim3 blk(256);
    dim3 grid_d(DMODEL / 128, MDIM / 128);   // (6, 64)
    dim3 grid_ff(DFF / 128, MDIM / 128);     // (16, 64)

    // QKV projections
    sgemm_kernel<0, 0><<<grid_d, blk>>>(x, Wq, bq, nullptr, pQ, MDIM, DMODEL, DMODEL);
    sgemm_kernel<0, 0><<<grid_d, blk>>>(x, Wk, bk, nullptr, pK, MDIM, DMODEL, DMODEL);
    sgemm_kernel<0, 0><<<grid_d, blk>>>(x, Wv, bv, nullptr, pV, MDIM, DMODEL, DMODEL);

    // fused attention
    attention_kernel<<<dim3(SEQ / 64, BATCH * NHEAD), blk>>>(pQ, pK, pV, mask, pAttn);

    // output projection + residual
    sgemm_kernel<0, 1><<<grid_d, blk>>>(pAttn, Wo, bo, x, pRes1, MDIM, DMODEL, DMODEL);
    layernorm_kernel<<<MDIM, blk>>>(pRes1, g1, be1, pX1);

    // FFN
    sgemm_kernel<1, 0><<<grid_ff, blk>>>(pX1, W1, b1, nullptr, pH, MDIM, DFF, DMODEL);
    sgemm_kernel<0, 1><<<grid_d, blk>>>(pH, W2, b2, pX1, pRes2, MDIM, DMODEL, DFF);
    layernorm_kernel<<<MDIM, blk>>>(pRes2, g2, be2, (float*)d_out);
}

// round 3
// speedup vs baseline: 2.7952x; 2.7952x over previous
#include <cuda_runtime.h>
#include <cuda_bf16.h>
#include <math.h>
#include <stdint.h>

// Problem dims
#define MDIM   8192
#define DMODEL 768
#define DFF    2048
#define SEQ    2048
#define BATCH  4
#define NHEAD  12
#define DK     64
#define NQKV   2304

typedef __nv_bfloat16 bf16;

// ---------------------------------------------------------------------------
// helpers
// ---------------------------------------------------------------------------
__device__ __forceinline__ uint32_t smem_u32(const void* p) {
    uint32_t a;
    asm("{ .reg .u64 t; cvta.to.shared.u64 t, %1; cvt.u32.u64 %0, t; }" : "=r"(a) : "l"(p));
    return a;
}
__device__ __forceinline__ void cpa16(uint32_t s, const void* g) {
    asm volatile("cp.async.cg.shared.global [%0], [%1], 16;" :: "r"(s), "l"(g));
}
#define CP_COMMIT() asm volatile("cp.async.commit_group;" ::: "memory")
#define CP_WAIT0()  asm volatile("cp.async.wait_group 0;" ::: "memory")
#define CP_WAIT1()  asm volatile("cp.async.wait_group 1;" ::: "memory")

#define LDSM4(R, addr) \
    asm volatile("ldmatrix.sync.aligned.m8n8.x4.shared.b16 {%0,%1,%2,%3}, [%4];" \
        : "=r"((R)[0]), "=r"((R)[1]), "=r"((R)[2]), "=r"((R)[3]) : "r"(addr))
#define LDSM4T(R, addr) \
    asm volatile("ldmatrix.sync.aligned.m8n8.x4.trans.shared.b16 {%0,%1,%2,%3}, [%4];" \
        : "=r"((R)[0]), "=r"((R)[1]), "=r"((R)[2]), "=r"((R)[3]) : "r"(addr))

__device__ __forceinline__ void mma16816(float* d, const uint32_t* a, uint32_t b0, uint32_t b1) {
    asm volatile("mma.sync.aligned.m16n8k16.row.col.f32.bf16.bf16.f32 "
        "{%0,%1,%2,%3}, {%4,%5,%6,%7}, {%8,%9}, {%0,%1,%2,%3};"
        : "+f"(d[0]), "+f"(d[1]), "+f"(d[2]), "+f"(d[3])
        : "r"(a[0]), "r"(a[1]), "r"(a[2]), "r"(a[3]), "r"(b0), "r"(b1));
}

// pack two f32 -> bf16x2 (lo = first elem, hi = second)
__device__ __forceinline__ uint32_t packbf2(float lo, float hi) {
    uint32_t r;
    asm("cvt.rn.bf16x2.f32 %0, %1, %2;" : "=r"(r) : "f"(hi), "f"(lo));
    return r;
}
// split pair (v0,v1) into hi bf16x2 and lo (residual) bf16x2
__device__ __forceinline__ void split2(float v0, float v1, uint32_t& hi, uint32_t& lo) {
    hi = packbf2(v0, v1);
    __nv_bfloat162 hh = *(__nv_bfloat162*)&hi;
    lo = packbf2(v0 - __bfloat162float(hh.x), v1 - __bfloat162float(hh.y));
}

// ---------------------------------------------------------------------------
// scratch (device globals)
// ---------------------------------------------------------------------------
__device__ bf16 g_QKVhi[(size_t)MDIM * NQKV];
__device__ bf16 g_QKVlo[(size_t)MDIM * NQKV];
__device__ bf16 g_Ahi[(size_t)MDIM * DMODEL];
__device__ bf16 g_Alo[(size_t)MDIM * DMODEL];
__device__ bf16 g_Hhi[(size_t)MDIM * DFF];
__device__ bf16 g_Hlo[(size_t)MDIM * DFF];
__device__ float g_res[(size_t)MDIM * DMODEL];
__device__ float g_x1[(size_t)MDIM * DMODEL];
// transposed weights [N][K]: qkv(2304x768) | wo(768x768) | w1(2048x768) | w2(768x2048)
#define OFF_WQKV 0
#define OFF_WO   (2304 * 768)
#define OFF_W1   (OFF_WO + 768 * 768)
#define OFF_W2   (OFF_W1 + 2048 * 768)
__device__ bf16 g_Whi[(size_t)768 * 7168];
__device__ bf16 g_Wlo[(size_t)768 * 7168];
__device__ float g_bqkv[NQKV];

// ---------------------------------------------------------------------------
// mma.sync split-bf16 GEMM: C[M,N] = A[M,K] @ Bt[N,K]^T + bias (+res)(+relu)
// CTA 128x128, BK=32, 8 warps (warp tile 64x32), cp.async double buffer.
// smem per stage: 4 tiles (Ahi,Alo,Bhi,Blo), each 128 rows x 80B = 10240B
// ---------------------------------------------------------------------------
#define G_STAGE 40960
#define GEMM_SMEM (2 * G_STAGE)

template<int DO_RELU, int DO_RES, int OUT_BF>
__global__ __launch_bounds__(256, 1)
void gemm_mma(const bf16* __restrict__ Ahi, const bf16* __restrict__ Alo,
              const bf16* __restrict__ Bhi, const bf16* __restrict__ Blo,
              const float* __restrict__ bias, const float* __restrict__ resid,
              float* __restrict__ Cf, bf16* __restrict__ Chi, bf16* __restrict__ Clo,
              int M, int N, int K)
{
    extern __shared__ char sm[];
    const uint32_t sbase = smem_u32(sm);
    const int tid = threadIdx.x;
    const int l = tid & 31;
    const int wid = tid >> 5;
    const int wm = wid & 1;        // 64-row half
    const int wn = wid >> 1;       // 32-col quarter
    const int row0 = blockIdx.y * 128;
    const int col0 = blockIdx.x * 128;

    float acc[4][4][4];
#pragma unroll
    for (int a = 0; a < 4; a++)
#pragma unroll
        for (int b = 0; b < 4; b++)
#pragma unroll
            for (int c = 0; c < 4; c++) acc[a][b][c] = 0.0f;

    const int NC = K / 32;

    // stage loader: each thread 2 granules per tile (512 granules/tile)
    auto load_stage = [&](int c, int s) {
        uint32_t st = sbase + s * G_STAGE;
        int k0 = c * 32;
#pragma unroll
        for (int i = 0; i < 2; i++) {
            int g = tid * 2 + i;            // 0..511
            int r = g >> 2, cq = g & 3;
            uint32_t sw = (uint32_t)r * 80u + cq * 16u;
            size_t ga = (size_t)(row0 + r) * K + k0 + cq * 8;
            size_t gb = (size_t)(col0 + r) * K + k0 + cq * 8;
            cpa16(st + sw, Ahi + ga);
            cpa16(st + 10240u + sw, Alo + ga);
            cpa16(st + 20480u + sw, Bhi + gb);
            cpa16(st + 30720u + sw, Blo + gb);
        }
        CP_COMMIT();
    };

    load_stage(0, 0);
    for (int c = 0; c < NC; c++) {
        const int s = c & 1;
        if (c + 1 < NC) { load_stage(c + 1, s ^ 1); CP_WAIT1(); }
        else           { CP_WAIT0(); }
        __syncthreads();

        uint32_t st = sbase + s * G_STAGE;
#pragma unroll
        for (int ks = 0; ks < 2; ks++) {
            uint32_t ah[4][4], al[4][4], bh[2][4], bl[2][4];
#pragma unroll
            for (int mi = 0; mi < 4; mi++) {
                uint32_t ar = st + (uint32_t)(wm * 64 + mi * 16 + (l & 15)) * 80u
                            + ks * 32u + (l >> 4) * 16u;
                LDSM4(ah[mi], ar);
                LDSM4(al[mi], ar + 10240u);
            }
#pragma unroll
            for (int jp = 0; jp < 2; jp++) {
                uint32_t br = st + 20480u
                            + (uint32_t)(wn * 32 + jp * 16 + ((l >> 4) * 8) + (l & 7)) * 80u
                            + ks * 32u + ((l >> 3) & 1) * 16u;
                LDSM4(bh[jp], br);
                LDSM4(bl[jp], br + 10240u);
            }
#pragma unroll
            for (int mi = 0; mi < 4; mi++)
#pragma unroll
                for (int ni = 0; ni < 4; ni++) {
                    const int jp = ni >> 1, e = (ni & 1) * 2;
                    mma16816(acc[mi][ni], ah[mi], bh[jp][e], bh[jp][e + 1]); // hi*hi
                    mma16816(acc[mi][ni], ah[mi], bl[jp][e], bl[jp][e + 1]); // hi*lo
                    mma16816(acc[mi][ni], al[mi], bh[jp][e], bh[jp][e + 1]); // lo*hi
                }
        }
        __syncthreads();
    }

    // epilogue
#pragma unroll
    for (int mi = 0; mi < 4; mi++) {
#pragma unroll
        for (int ni = 0; ni < 4; ni++) {
            int row = row0 + wm * 64 + mi * 16 + (l >> 2);
            int col = col0 + wn * 32 + ni * 8 + (l & 3) * 2;
            float b0 = __ldg(&bias[col]), b1 = __ldg(&bias[col + 1]);
            float v00 = acc[mi][ni][0] + b0, v01 = acc[mi][ni][1] + b1;
            float v10 = acc[mi][ni][2] + b0, v11 = acc[mi][ni][3] + b1;
            size_t o0 = (size_t)row * N + col;
            size_t o1 = (size_t)(row + 8) * N + col;
            if (DO_RES) {
                float2 r0 = *(const float2*)&resid[o0];
                float2 r1 = *(const float2*)&resid[o1];
                v00 += r0.x; v01 += r0.y; v10 += r1.x; v11 += r1.y;
            }
            if (DO_RELU) {
                v00 = fmaxf(v00, 0.0f); v01 = fmaxf(v01, 0.0f);
                v10 = fmaxf(v10, 0.0f); v11 = fmaxf(v11, 0.0f);
            }
            if (OUT_BF) {
                uint32_t hi, lo;
                split2(v00, v01, hi, lo);
                *(uint32_t*)&Chi[o0] = hi; *(uint32_t*)&Clo[o0] = lo;
                split2(v10, v11, hi, lo);
                *(uint32_t*)&Chi[o1] = hi; *(uint32_t*)&Clo[o1] = lo;
            } else {
                *(float2*)&Cf[o0] = make_float2(v00, v01);
                *(float2*)&Cf[o1] = make_float2(v10, v11);
            }
        }
    }
}

// ---------------------------------------------------------------------------
// mma.sync flash attention, split bf16, fp32 online softmax
// grid (SEQ/128, B*H), block 256; warp = 16 query rows; KV tile 64
// smem: Qhi[128x144] Qlo | 2 stages x {Khi,Klo,Vhi,Vlo (64x144) + mask(256B)}
// ---------------------------------------------------------------------------
#define AQ_BYTES 18432              // 128*144
#define KV_TILE  9216               // 64*144
#define KV_STAGE 37120              // 4*9216 + 256
#define ATT_SMEM (2 * AQ_BYTES + 2 * KV_STAGE)

__global__ __launch_bounds__(256, 1)
void attention_mma(const bf16* __restrict__ QKVhi, const bf16* __restrict__ QKVlo,
                   const float* __restrict__ mask,
                   bf16* __restrict__ Ohi, bf16* __restrict__ Olo)
{
    extern __shared__ char sm[];
    const uint32_t sbase = smem_u32(sm);
    const int tid = threadIdx.x;
    const int l = tid & 31;
    const int w = tid >> 5;
    const int bh = blockIdx.y;
    const int b = bh / NHEAD;
    const int h = bh % NHEAD;
    const int q0 = blockIdx.x * 128;

    // ---- load Q tile (hi+lo), 128 rows x 64 bf16 ----
#pragma unroll
    for (int i = 0; i < 4; i++) {
        int g = tid * 4 + i;               // 0..1023
        int r = g >> 3, gq = g & 7;
        uint32_t sw = (uint32_t)r * 144u + gq * 16u;
        size_t ga = (size_t)(b * SEQ + q0 + r) * NQKV + h * DK + gq * 8;
        cpa16(sbase + sw, QKVhi + ga);
        cpa16(sbase + AQ_BYTES + sw, QKVlo + ga);
    }
    CP_COMMIT();

    auto load_kv = [&](int kt, int s) {
        uint32_t st = sbase + 2 * AQ_BYTES + s * KV_STAGE;
        int k0 = kt * 64;
#pragma unroll
        for (int i = 0; i < 2; i++) {
            int g = tid * 2 + i;           // 0..511
            int r = g >> 3, gq = g & 7;
            uint32_t sw = (uint32_t)r * 144u + gq * 16u;
            size_t gk = (size_t)(b * SEQ + k0 + r) * NQKV + 768 + h * DK + gq * 8;
            size_t gv = (size_t)(b * SEQ + k0 + r) * NQKV + 1536 + h * DK + gq * 8;
            cpa16(st + sw, QKVhi + gk);
            cpa16(st + KV_TILE + sw, QKVlo + gk);
            cpa16(st + 2 * KV_TILE + sw, QKVhi + gv);
            cpa16(st + 3 * KV_TILE + sw, QKVlo + gv);
        }
        if (tid < 16)
            cpa16(st + 4 * KV_TILE + tid * 16, mask + b * SEQ + k0 + tid * 4);
        CP_COMMIT();
    };

    load_kv(0, 0);
    CP_WAIT1();          // Q group done (kv0 may still be in flight)
    __syncthreads();

    // ---- Q fragments (persistent) ----
    uint32_t qh[4][4], ql[4][4];
#pragma unroll
    for (int ks = 0; ks < 4; ks++) {
        uint32_t ar = sbase + (uint32_t)(w * 16 + (l & 15)) * 144u + ks * 32u + (l >> 4) * 16u;
        LDSM4(qh[ks], ar);
        LDSM4(ql[ks], ar + AQ_BYTES);
    }

    float m0 = -1e30f, m1 = -1e30f, l0 = 0.0f, l1 = 0.0f;
    float o[8][4];
#pragma unroll
    for (int nt = 0; nt < 8; nt++)
#pragma unroll
        for (int c = 0; c < 4; c++) o[nt][c] = 0.0f;

    const int NKT = SEQ / 64;
    for (int kt = 0; kt < NKT; kt++) {
        const int s = kt & 1;
        if (kt + 1 < NKT) { load_kv(kt + 1, s ^ 1); CP_WAIT1(); }
        else             { CP_WAIT0(); }
        __syncthreads();

        uint32_t st = sbase + 2 * AQ_BYTES + s * KV_STAGE;
        const float* msk = (const float*)(sm + (st - sbase) + 4 * KV_TILE);

        // ---- scores: S = Q K^T ----
        float sc[8][4];
#pragma unroll
        for (int nt = 0; nt < 8; nt++)
#pragma unroll
            for (int c = 0; c < 4; c++) sc[nt][c] = 0.0f;

#pragma unroll
        for (int ks = 0; ks < 4; ks++) {
#pragma unroll
            for (int jp = 0; jp < 4; jp++) {
                uint32_t br = st + (uint32_t)(jp * 16 + ((l >> 4) * 8) + (l & 7)) * 144u
                            + ks * 32u + ((l >> 3) & 1) * 16u;
                uint32_t kh[4], kl[4];
                LDSM4(kh, br);
                LDSM4(kl, br + KV_TILE);
                mma16816(sc[2 * jp],     qh[ks], kh[0], kh[1]);
                mma16816(sc[2 * jp],     qh[ks], kl[0], kl[1]);
                mma16816(sc[2 * jp],     ql[ks], kh[0], kh[1]);
                mma16816(sc[2 * jp + 1], qh[ks], kh[2], kh[3]);
                mma16816(sc[2 * jp + 1], qh[ks], kl[2], kl[3]);
                mma16816(sc[2 * jp + 1], ql[ks], kh[2], kh[3]);
            }
        }

        // ---- scale + mask + online softmax ----
        float mx0 = -1e30f, mx1 = -1e30f;
#pragma unroll
        for (int nt = 0; nt < 8; nt++) {
            int col = nt * 8 + (l & 3) * 2;
            float k0m = msk[col] * (-1e9f), k1m = msk[col + 1] * (-1e9f);
            sc[nt][0] = fmaf(sc[nt][0], 0.125f, k0m);
            sc[nt][1] = fmaf(sc[nt][1], 0.125f, k1m);
            sc[nt][2] = fmaf(sc[nt][2], 0.125f, k0m);
            sc[nt][3] = fmaf(sc[nt][3], 0.125f, k1m);
            mx0 = fmaxf(mx0, fmaxf(sc[nt][0], sc[nt][1]));
            mx1 = fmaxf(mx1, fmaxf(sc[nt][2], sc[nt][3]));
        }
        mx0 = fmaxf(mx0, __shfl_xor_sync(0xffffffffu, mx0, 1));
        mx0 = fmaxf(mx0, __shfl_xor_sync(0xffffffffu, mx0, 2));
        mx1 = fmaxf(mx1, __shfl_xor_sync(0xffffffffu, mx1, 1));
        mx1 = fmaxf(mx1, __shfl_xor_sync(0xffffffffu, mx1, 2));

        float nm0 = fmaxf(m0, mx0), nm1 = fmaxf(m1, mx1);
        float al0 = __expf(m0 - nm0), al1 = __expf(m1 - nm1);
        m0 = nm0; m1 = nm1;

        float rs0 = 0.0f, rs1 = 0.0f;
#pragma unroll
        for (int nt = 0; nt < 8; nt++) {
            sc[nt][0] = __expf(sc[nt][0] - nm0);
            sc[nt][1] = __expf(sc[nt][1] - nm0);
            sc[nt][2] = __expf(sc[nt][2] - nm1);
            sc[nt][3] = __expf(sc[nt][3] - nm1);
            rs0 += sc[nt][0] + sc[nt][1];
            rs1 += sc[nt][2] + sc[nt][3];
        }
        rs0 += __shfl_xor_sync(0xffffffffu, rs0, 1);
        rs0 += __shfl_xor_sync(0xffffffffu, rs0, 2);
        rs1 += __shfl_xor_sync(0xffffffffu, rs1, 1);
        rs1 += __shfl_xor_sync(0xffffffffu, rs1, 2);
        l0 = l0 * al0 + rs0;
        l1 = l1 * al1 + rs1;
#pragma unroll
        for (int nt = 0; nt < 8; nt++) {
            o[nt][0] *= al0; o[nt][1] *= al0;
            o[nt][2] *= al1; o[nt][3] *= al1;
        }

        // ---- O += P V ----
#pragma unroll
        for (int j = 0; j < 4; j++) {
            uint32_t ph[4], pl[4];
            split2(sc[2 * j][0],     sc[2 * j][1],     ph[0], pl[0]);
            split2(sc[2 * j][2],     sc[2 * j][3],     ph[1], pl[1]);
            split2(sc[2 * j + 1][0], sc[2 * j + 1][1], ph[2], pl[2]);
            split2(sc[2 * j + 1][2], sc[2 * j + 1][3], ph[3], pl[3]);
#pragma unroll
            for (int np = 0; np < 4; np++) {
                uint32_t vr = st + 2 * KV_TILE
                            + (uint32_t)(j * 16 + ((l >> 3) & 1) * 8 + (l & 7)) * 144u
                            + (np * 16 + (l >> 4) * 8) * 2u;
                uint32_t vh[4], vl[4];
                LDSM4T(vh, vr);
                LDSM4T(vl, vr + KV_TILE);
                mma16816(o[2 * np],     ph, vh[0], vh[1]);
                mma16816(o[2 * np],     ph, vl[0], vl[1]);
                mma16816(o[2 * np],     pl, vh[0], vh[1]);
                mma16816(o[2 * np + 1], ph, vh[2], vh[3]);
                mma16816(o[2 * np + 1], ph, vl[2], vl[3]);
                mma16816(o[2 * np + 1], pl, vh[2], vh[3]);
            }
        }
        __syncthreads();
    }

    // ---- epilogue: normalize + split store (head-concat layout) ----
    float inv0 = 1.0f / l0, inv1 = 1.0f / l1;
#pragma unroll
    for (int nt = 0; nt < 8; nt++) {
        int col = h * DK + nt * 8 + (l & 3) * 2;
        size_t r0 = (size_t)(b * SEQ + q0 + w * 16 + (l >> 2)) * DMODEL + col;
        size_t r1 = r0 + 8 * DMODEL;
        uint32_t hi, lo;
        split2(o[nt][0] * inv0, o[nt][1] * inv0, hi, lo);
        *(uint32_t*)&Ohi[r0] = hi; *(uint32_t*)&Olo[r0] = lo;
        split2(o[nt][2] * inv1, o[nt][3] * inv1, hi, lo);
        *(uint32_t*)&Ohi[r1] = hi; *(uint32_t*)&Olo[r1] = lo;
    }
}

// ---------------------------------------------------------------------------
// conversion kernels
// ---------------------------------------------------------------------------
__global__ __launch_bounds__(256)
void split_f32(const float* __restrict__ in, bf16* __restrict__ hi,
               bf16* __restrict__ lo, int n4)
{
    int i = blockIdx.x * 256 + threadIdx.x;
    if (i >= n4) return;
    float4 v = ((const float4*)in)[i];
    uint32_t h0, l0, h1, l1;
    split2(v.x, v.y, h0, l0);
    split2(v.z, v.w, h1, l1);
    *(uint32_t*)&hi[i * 4]     = h0;
    *(uint32_t*)&hi[i * 4 + 2] = h1;
    *(uint32_t*)&lo[i * 4]     = l0;
    *(uint32_t*)&lo[i * 4 + 2] = l1;
}

// W [K,N] f32 -> out[N][K] split bf16 (transpose)
__global__ __launch_bounds__(256)
void wtrans(const float* __restrict__ W, bf16* __restrict__ hi,
            bf16* __restrict__ lo, int K, int N)
{
    __shared__ float t[32][33];
    const int n0 = blockIdx.x * 32, k0 = blockIdx.y * 32;
    const int tx = threadIdx.x & 31, ty = threadIdx.x >> 5;
#pragma unroll
    for (int i = 0; i < 4; i++)
        t[ty + 8 * i][tx] = W[(size_t)(k0 + ty + 8 * i) * N + n0 + tx];
    __syncthreads();
#pragma unroll
    for (int i = 0; i < 4; i++) {
        float v = t[tx][ty + 8 * i];
        size_t off = (size_t)(n0 + ty + 8 * i) * K + k0 + tx;
        __nv_bfloat16 hb = __float2bfloat16(v);
        hi[off] = hb;
        lo[off] = __float2bfloat16(v - __bfloat162float(hb));
    }
}

__global__ void concat_bias(const float* bq, const float* bk, const float* bv, float* out)
{
    int i = blockIdx.x * 256 + threadIdx.x;
    if (i < 768) out[i] = bq[i];
    else if (i < 1536) out[i] = bk[i - 768];
    else if (i < 2304) out[i] = bv[i - 1536];
}

// ---------------------------------------------------------------------------
// LayerNorm (768); optionally emits split bf16 alongside f32
// ---------------------------------------------------------------------------
template<int EMIT_SPLIT>
__global__ __launch_bounds__(256)
void layernorm_kernel(const float* __restrict__ X, const float* __restrict__ gamma,
                      const float* __restrict__ beta, float* __restrict__ Y,
                      bf16* __restrict__ Yhi, bf16* __restrict__ Ylo)
{
    const int row = blockIdx.x;
    const int tid = threadIdx.x;
    const float* x = X + (size_t)row * DMODEL;

    float v[3];
    float sum = 0.0f, sq = 0.0f;
#pragma unroll
    for (int i = 0; i < 3; i++) {
        v[i] = x[tid + i * 256];
        sum += v[i];
        sq = fmaf(v[i], v[i], sq);
    }
#pragma unroll
    for (int off = 16; off > 0; off >>= 1) {
        sum += __shfl_xor_sync(0xffffffffu, sum, off);
        sq  += __shfl_xor_sync(0xffffffffu, sq,  off);
    }
    __shared__ float rsm[8], rqm[8], bc[2];
    int w = tid >> 5, lane = tid & 31;
    if (lane == 0) { rsm[w] = sum; rqm[w] = sq; }
    __syncthreads();
    if (tid == 0) {
        float s = 0.0f, q = 0.0f;
#pragma unroll
        for (int i = 0; i < 8; i++) { s += rsm[i]; q += rqm[i]; }
        float mean = s * (1.0f / DMODEL);
        float var = q * (1.0f / DMODEL) - mean * mean;
        bc[0] = mean;
        bc[1] = rsqrtf(var + 1e-3f);
    }
    __syncthreads();
    float mean = bc[0], inv = bc[1];
#pragma unroll
    for (int i = 0; i < 3; i++) {
        int col = tid + i * 256;
        float y = (v[i] - mean) * inv * gamma[col] + beta[col];
        size_t off = (size_t)row * DMODEL + col;
        Y[off] = y;
        if (EMIT_SPLIT) {
            __nv_bfloat16 hb = __float2bfloat16(y);
            Yhi[off] = hb;
            Ylo[off] = __float2bfloat16(y - __bfloat162float(hb));
        }
    }
}

// ---------------------------------------------------------------------------
// launch
// ---------------------------------------------------------------------------
extern "C" void kernel_launch(void* const* d_in, const int* in_sizes, int n_in,
                              void* d_out, int out_size)
{
    const float* x    = (const float*)d_in[0];
    const float* mask = (const float*)d_in[1];
    const float* Wq   = (const float*)d_in[2];
    const float* bq   = (const float*)d_in[3];
    const float* Wk   = (const float*)d_in[4];
    const float* bk   = (const float*)d_in[5];
    const float* Wv   = (const float*)d_in[6];
    const float* bv   = (const float*)d_in[7];
    const float* Wo   = (const float*)d_in[8];
    const float* bo   = (const float*)d_in[9];
    const float* W1   = (const float*)d_in[10];
    const float* b1   = (const float*)d_in[11];
    const float* W2   = (const float*)d_in[12];
    const float* b2   = (const float*)d_in[13];
    const float* g1   = (const float*)d_in[14];
    const float* be1  = (const float*)d_in[15];
    const float* g2   = (const float*)d_in[16];
    const float* be2  = (const float*)d_in[17];

    float *pRes, *pX1, *pBqkv;
    bf16 *pQKVhi, *pQKVlo, *pAhi, *pAlo, *pHhi, *pHlo, *pWhi, *pWlo;
    cudaGetSymbolAddress((void**)&pQKVhi, g_QKVhi);
    cudaGetSymbolAddress((void**)&pQKVlo, g_QKVlo);
    cudaGetSymbolAddress((void**)&pAhi,   g_Ahi);
    cudaGetSymbolAddress((void**)&pAlo,   g_Alo);
    cudaGetSymbolAddress((void**)&pHhi,   g_Hhi);
    cudaGetSymbolAddress((void**)&pHlo,   g_Hlo);
    cudaGetSymbolAddress((void**)&pWhi,   g_Whi);
    cudaGetSymbolAddress((void**)&pWlo,   g_Wlo);
    cudaGetSymbolAddress((void**)&pRes,   g_res);
    cudaGetSymbolAddress((void**)&pX1,    g_x1);
    cudaGetSymbolAddress((void**)&pBqkv,  g_bqkv);

    static bool attr_set = false;
    if (!attr_set) {
        cudaFuncSetAttribute(gemm_mma<0, 0, 1>, cudaFuncAttributeMaxDynamicSharedMemorySize, GEMM_SMEM);
        cudaFuncSetAttribute(gemm_mma<0, 1, 0>, cudaFuncAttributeMaxDynamicSharedMemorySize, GEMM_SMEM);
        cudaFuncSetAttribute(gemm_mma<1, 0, 1>, cudaFuncAttributeMaxDynamicSharedMemorySize, GEMM_SMEM);
        cudaFuncSetAttribute(attention_mma, cudaFuncAttributeMaxDynamicSharedMemorySize, ATT_SMEM);
        attr_set = true;
    }

    dim3 blk(256);

    // weight prep
    wtrans<<<dim3(24, 24), blk>>>(Wq, pWhi + OFF_WQKV,                 pWlo + OFF_WQKV,                 768, 768);
    wtrans<<<dim3(24, 24), blk>>>(Wk, pWhi + OFF_WQKV + 768 * 768,     pWlo + OFF_WQKV + 768 * 768,     768, 768);
    wtrans<<<dim3(24, 24), blk>>>(Wv, pWhi + OFF_WQKV + 2 * 768 * 768, pWlo + OFF_WQKV + 2 * 768 * 768, 768, 768);
    wtrans<<<dim3(24, 24), blk>>>(Wo, pWhi + OFF_WO, pWlo + OFF_WO, 768, 768);
    wtrans<<<dim3(64, 24), blk>>>(W1, pWhi + OFF_W1, pWlo + OFF_W1, 768, DFF);
    wtrans<<<dim3(24, 64), blk>>>(W2, pWhi + OFF_W2, pWlo + OFF_W2, DFF, 768);
    concat_bias<<<9, 256>>>(bq, bk, bv, pBqkv);

    // x -> split bf16
    split_f32<<<(MDIM * DMODEL / 4 + 255) / 256, blk>>>(x, pAhi, pAlo, MDIM * DMODEL / 4);

    // fused QKV: [8192,768]@[768,2304] -> split bf16 QKV
    gemm_mma<0, 0, 1><<<dim3(NQKV / 128, MDIM / 128), blk, GEMM_SMEM>>>(
        pAhi, pAlo, pWhi + OFF_WQKV, pWlo + OFF_WQKV, pBqkv, nullptr,
        nullptr, pQKVhi, pQKVlo, MDIM, NQKV, DMODEL);

    // attention -> split bf16 attn-out (into g_Ahi/g_Alo)
    attention_mma<<<dim3(SEQ / 128, BATCH * NHEAD), blk, ATT_SMEM>>>(
        pQKVhi, pQKVlo, mask, pAhi, pAlo);

    // O projection + residual(x) -> g_res (f32)
    gemm_mma<0, 1, 0><<<dim3(DMODEL / 128, MDIM / 128), blk, GEMM_SMEM>>>(
        pAhi, pAlo, pWhi + OFF_WO, pWlo + OFF_WO, bo, x,
        pRes, nullptr, nullptr, MDIM, DMODEL, DMODEL);

    // LN1 -> x1 f32 + split bf16 (overwrites g_Ahi/g_Alo)
    layernorm_kernel<1><<<MDIM, blk>>>(pRes, g1, be1, pX1, pAhi, pAlo);

    // FFN1: relu(x1@W1+b1) -> H split bf16
    gemm_mma<1, 0, 1><<<dim3(DFF / 128, MDIM / 128), blk, GEMM_SMEM>>>(
        pAhi, pAlo, pWhi + OFF_W1, pWlo + OFF_W1, b1, nullptr,
        nullptr, pHhi, pHlo, MDIM, DFF, DMODEL);

    // FFN2: H@W2+b2+x1 -> g_res
    gemm_mma<0, 1, 0><<<dim3(DMODEL / 128, MDIM / 128), blk, GEMM_SMEM>>>(
        pHhi, pHlo, pWhi + OFF_W2, pWlo + OFF_W2, b2, pX1,
        pRes, nullptr, nullptr, MDIM, DMODEL, DFF);

    // LN2 -> out
    layernorm_kernel<0><<<MDIM, blk>>>(pRes, g2, be2, (float*)d_out, nullptr, nullptr);
}

// round 4
// speedup vs baseline: 3.0437x; 1.0889x over previous
#include <cuda_runtime.h>
#include <cuda_bf16.h>
#include <math.h>
#include <stdint.h>

// Problem dims
#define MDIM   8192
#define DMODEL 768
#define DFF    2048
#define SEQ    2048
#define BATCH  4
#define NHEAD  12
#define DK     64
#define NQKV   2304

typedef __nv_bfloat16 bf16;

// ---------------------------------------------------------------------------
// helpers
// ---------------------------------------------------------------------------
__device__ __forceinline__ uint32_t smem_u32(const void* p) {
    uint32_t a;
    asm("{ .reg .u64 t; cvta.to.shared.u64 t, %1; cvt.u32.u64 %0, t; }" : "=r"(a) : "l"(p));
    return a;
}
__device__ __forceinline__ void cpa16(uint32_t s, const void* g) {
    asm volatile("cp.async.cg.shared.global [%0], [%1], 16;" :: "r"(s), "l"(g));
}
#define CP_COMMIT() asm volatile("cp.async.commit_group;" ::: "memory")
#define CP_WAIT0()  asm volatile("cp.async.wait_group 0;" ::: "memory")
#define CP_WAIT1()  asm volatile("cp.async.wait_group 1;" ::: "memory")
#define CP_WAIT2()  asm volatile("cp.async.wait_group 2;" ::: "memory")

#define LDSM4(R, addr) \
    asm volatile("ldmatrix.sync.aligned.m8n8.x4.shared.b16 {%0,%1,%2,%3}, [%4];" \
        : "=r"((R)[0]), "=r"((R)[1]), "=r"((R)[2]), "=r"((R)[3]) : "r"(addr))
#define LDSM4T(R, addr) \
    asm volatile("ldmatrix.sync.aligned.m8n8.x4.trans.shared.b16 {%0,%1,%2,%3}, [%4];" \
        : "=r"((R)[0]), "=r"((R)[1]), "=r"((R)[2]), "=r"((R)[3]) : "r"(addr))

__device__ __forceinline__ void mma16816(float* d, const uint32_t* a, uint32_t b0, uint32_t b1) {
    asm volatile("mma.sync.aligned.m16n8k16.row.col.f32.bf16.bf16.f32 "
        "{%0,%1,%2,%3}, {%4,%5,%6,%7}, {%8,%9}, {%0,%1,%2,%3};"
        : "+f"(d[0]), "+f"(d[1]), "+f"(d[2]), "+f"(d[3])
        : "r"(a[0]), "r"(a[1]), "r"(a[2]), "r"(a[3]), "r"(b0), "r"(b1));
}

__device__ __forceinline__ uint32_t packbf2(float lo, float hi) {
    uint32_t r;
    asm("cvt.rn.bf16x2.f32 %0, %1, %2;" : "=r"(r) : "f"(hi), "f"(lo));
    return r;
}
__device__ __forceinline__ void split2(float v0, float v1, uint32_t& hi, uint32_t& lo) {
    hi = packbf2(v0, v1);
    __nv_bfloat162 hh = *(__nv_bfloat162*)&hi;
    lo = packbf2(v0 - __bfloat162float(hh.x), v1 - __bfloat162float(hh.y));
}

// ---------------------------------------------------------------------------
// scratch
// ---------------------------------------------------------------------------
__device__ bf16 g_QKVhi[(size_t)MDIM * NQKV];
__device__ bf16 g_QKVlo[(size_t)MDIM * NQKV];
__device__ bf16 g_Ahi[(size_t)MDIM * DMODEL];
__device__ bf16 g_Alo[(size_t)MDIM * DMODEL];
__device__ bf16 g_Hhi[(size_t)MDIM * DFF];
__device__ bf16 g_Hlo[(size_t)MDIM * DFF];
__device__ float g_res[(size_t)MDIM * DMODEL];
__device__ float g_x1[(size_t)MDIM * DMODEL];
#define OFF_WQKV 0
#define OFF_WO   (2304 * 768)
#define OFF_W1   (OFF_WO + 768 * 768)
#define OFF_W2   (OFF_W1 + 2048 * 768)
__device__ bf16 g_Whi[(size_t)768 * 7168];
__device__ bf16 g_Wlo[(size_t)768 * 7168];
__device__ float g_bqkv[NQKV];

// ---------------------------------------------------------------------------
// mma.sync split-bf16 GEMM.  CTA tile 128 x (32*NI), BK=32, 8 warps
// (warp tile 64 x 8*NI), 3-stage cp.async pipeline.
// smem/stage: Ahi(10240) Alo(10240) Bhi(2560*NI) Blo(2560*NI)
// ---------------------------------------------------------------------------
template<int NI, int DO_RELU, int DO_RES, int OUT_BF>
__global__ __launch_bounds__(256, 1)
void gemm_mma(const bf16* __restrict__ Ahi, const bf16* __restrict__ Alo,
              const bf16* __restrict__ Bhi, const bf16* __restrict__ Blo,
              const float* __restrict__ bias, const float* __restrict__ resid,
              float* __restrict__ Cf, bf16* __restrict__ Chi, bf16* __restrict__ Clo,
              int M, int N, int K)
{
    constexpr int TN      = 32 * NI;              // CTA N
    constexpr uint32_t BB = 2560u * NI;           // bytes per B tile
    constexpr uint32_t ALO = 10240u;
    constexpr uint32_t BHI = 20480u;
    constexpr uint32_t BLO = 20480u + BB;
    constexpr uint32_t STG = 20480u + 2u * BB;    // stage bytes
    constexpr int NGRAN   = 1024 + 256 * NI;      // 16B granules per stage
    constexpr int GPT     = NGRAN / 256;          // granules per thread

    extern __shared__ char sm[];
    const uint32_t sbase = smem_u32(sm);
    const int tid = threadIdx.x;
    const int l = tid & 31;
    const int wid = tid >> 5;
    const int wm = wid & 1;
    const int wn = wid >> 1;
    const int row0 = blockIdx.y * 128;
    const int col0 = blockIdx.x * TN;

    float acc[4][NI][4];
#pragma unroll
    for (int a = 0; a < 4; a++)
#pragma unroll
        for (int b = 0; b < NI; b++)
#pragma unroll
            for (int c = 0; c < 4; c++) acc[a][b][c] = 0.0f;

    const int NC = K / 32;

    auto load_stage = [&](int c, int s) {
        uint32_t st = sbase + (uint32_t)s * STG;
        int k0 = c * 32;
#pragma unroll
        for (int i = 0; i < GPT; i++) {
            int g = tid + i * 256;
            if (g < 1024) {
                int t = g & 511;
                int r = t >> 2, cq = t & 3;
                uint32_t sw = (uint32_t)r * 80u + cq * 16u;
                size_t ga = (size_t)(row0 + r) * K + k0 + cq * 8;
                if (g < 512) cpa16(st + sw, Ahi + ga);
                else         cpa16(st + ALO + sw, Alo + ga);
            } else {
                int t = g - 1024;
                int tt = t % (128 * NI);
                int r = tt >> 2, cq = tt & 3;
                uint32_t sw = (uint32_t)r * 80u + cq * 16u;
                size_t gb = (size_t)(col0 + r) * K + k0 + cq * 8;
                if (t < 128 * NI) cpa16(st + BHI + sw, Bhi + gb);
                else              cpa16(st + BLO + sw, Blo + gb);
            }
        }
        CP_COMMIT();
    };

    load_stage(0, 0);
    load_stage(1, 1);

    for (int c = 0; c < NC; c++) {
        if (c == NC - 1) { CP_WAIT0(); } else { CP_WAIT1(); }
        __syncthreads();
        if (c + 2 < NC) load_stage(c + 2, (c + 2) % 3);

        uint32_t st = sbase + (uint32_t)(c % 3) * STG;
#pragma unroll
        for (int ks = 0; ks < 2; ks++) {
            uint32_t ah[4][4], al[4][4], bh[NI / 2][4], bl[NI / 2][4];
#pragma unroll
            for (int mi = 0; mi < 4; mi++) {
                uint32_t ar = st + (uint32_t)(wm * 64 + mi * 16 + (l & 15)) * 80u
                            + ks * 32u + (l >> 4) * 16u;
                LDSM4(ah[mi], ar);
                LDSM4(al[mi], ar + ALO);
            }
#pragma unroll
            for (int jp = 0; jp < NI / 2; jp++) {
                uint32_t br = st + BHI
                            + (uint32_t)(wn * (NI * 8) + jp * 16 + ((l >> 4) * 8) + (l & 7)) * 80u
                            + ks * 32u + ((l >> 3) & 1) * 16u;
                LDSM4(bh[jp], br);
                LDSM4(bl[jp], br + BB);
            }
#pragma unroll
            for (int mi = 0; mi < 4; mi++)
#pragma unroll
                for (int ni = 0; ni < NI; ni++) {
                    const int jp = ni >> 1, e = (ni & 1) * 2;
                    mma16816(acc[mi][ni], ah[mi], bh[jp][e], bh[jp][e + 1]);
                    mma16816(acc[mi][ni], ah[mi], bl[jp][e], bl[jp][e + 1]);
                    mma16816(acc[mi][ni], al[mi], bh[jp][e], bh[jp][e + 1]);
                }
        }
    }

    // epilogue
#pragma unroll
    for (int mi = 0; mi < 4; mi++) {
#pragma unroll
        for (int ni = 0; ni < NI; ni++) {
            int row = row0 + wm * 64 + mi * 16 + (l >> 2);
            int col = col0 + wn * (NI * 8) + ni * 8 + (l & 3) * 2;
            float b0 = __ldg(&bias[col]), b1 = __ldg(&bias[col + 1]);
            float v00 = acc[mi][ni][0] + b0, v01 = acc[mi][ni][1] + b1;
            float v10 = acc[mi][ni][2] + b0, v11 = acc[mi][ni][3] + b1;
            size_t o0 = (size_t)row * N + col;
            size_t o1 = (size_t)(row + 8) * N + col;
            if (DO_RES) {
                float2 r0 = *(const float2*)&resid[o0];
                float2 r1 = *(const float2*)&resid[o1];
                v00 += r0.x; v01 += r0.y; v10 += r1.x; v11 += r1.y;
            }
            if (DO_RELU) {
                v00 = fmaxf(v00, 0.0f); v01 = fmaxf(v01, 0.0f);
                v10 = fmaxf(v10, 0.0f); v11 = fmaxf(v11, 0.0f);
            }
            if (OUT_BF) {
                uint32_t hi, lo;
                split2(v00, v01, hi, lo);
                *(uint32_t*)&Chi[o0] = hi; *(uint32_t*)&Clo[o0] = lo;
                split2(v10, v11, hi, lo);
                *(uint32_t*)&Chi[o1] = hi; *(uint32_t*)&Clo[o1] = lo;
            } else {
                *(float2*)&Cf[o0] = make_float2(v00, v01);
                *(float2*)&Cf[o1] = make_float2(v10, v11);
            }
        }
    }
}

// ---------------------------------------------------------------------------
// mma.sync flash attention, split bf16, 3-stage KV pipeline
// ---------------------------------------------------------------------------
#define AQ_BYTES 18432
#define KV_TILE  9216
#define KV_STAGE 37120
#define ATT_SMEM (2 * AQ_BYTES + 3 * KV_STAGE)

__global__ __launch_bounds__(256, 1)
void attention_mma(const bf16* __restrict__ QKVhi, const bf16* __restrict__ QKVlo,
                   const float* __restrict__ mask,
                   bf16* __restrict__ Ohi, bf16* __restrict__ Olo)
{
    extern __shared__ char sm[];
    const uint32_t sbase = smem_u32(sm);
    const int tid = threadIdx.x;
    const int l = tid & 31;
    const int w = tid >> 5;
    const int bh = blockIdx.y;
    const int b = bh / NHEAD;
    const int h = bh % NHEAD;
    const int q0 = blockIdx.x * 128;

    // Q tile (hi+lo)
#pragma unroll
    for (int i = 0; i < 4; i++) {
        int g = tid * 4 + i;
        int r = g >> 3, gq = g & 7;
        uint32_t sw = (uint32_t)r * 144u + gq * 16u;
        size_t ga = (size_t)(b * SEQ + q0 + r) * NQKV + h * DK + gq * 8;
        cpa16(sbase + sw, QKVhi + ga);
        cpa16(sbase + AQ_BYTES + sw, QKVlo + ga);
    }
    CP_COMMIT();

    auto load_kv = [&](int kt, int s) {
        uint32_t st = sbase + 2 * AQ_BYTES + (uint32_t)s * KV_STAGE;
        int k0 = kt * 64;
#pragma unroll
        for (int i = 0; i < 2; i++) {
            int g = tid * 2 + i;
            int r = g >> 3, gq = g & 7;
            uint32_t sw = (uint32_t)r * 144u + gq * 16u;
            size_t gk = (size_t)(b * SEQ + k0 + r) * NQKV + 768 + h * DK + gq * 8;
            size_t gv = (size_t)(b * SEQ + k0 + r) * NQKV + 1536 + h * DK + gq * 8;
            cpa16(st + sw, QKVhi + gk);
            cpa16(st + KV_TILE + sw, QKVlo + gk);
            cpa16(st + 2 * KV_TILE + sw, QKVhi + gv);
            cpa16(st + 3 * KV_TILE + sw, QKVlo + gv);
        }
        if (tid < 16)
            cpa16(st + 4 * KV_TILE + tid * 16, mask + b * SEQ + k0 + tid * 4);
        CP_COMMIT();
    };

    load_kv(0, 0);
    load_kv(1, 1);
    CP_WAIT2();          // Q done
    __syncthreads();

    uint32_t qh[4][4], ql[4][4];
#pragma unroll
    for (int ks = 0; ks < 4; ks++) {
        uint32_t ar = sbase + (uint32_t)(w * 16 + (l & 15)) * 144u + ks * 32u + (l >> 4) * 16u;
        LDSM4(qh[ks], ar);
        LDSM4(ql[ks], ar + AQ_BYTES);
    }

    float m0 = -1e30f, m1 = -1e30f, l0 = 0.0f, l1 = 0.0f;
    float o[8][4];
#pragma unroll
    for (int nt = 0; nt < 8; nt++)
#pragma unroll
        for (int c = 0; c < 4; c++) o[nt][c] = 0.0f;

    const int NKT = SEQ / 64;
    for (int kt = 0; kt < NKT; kt++) {
        if (kt == NKT - 1) { CP_WAIT0(); } else { CP_WAIT1(); }
        __syncthreads();
        if (kt + 2 < NKT) load_kv(kt + 2, (kt + 2) % 3);

        uint32_t st = sbase + 2 * AQ_BYTES + (uint32_t)(kt % 3) * KV_STAGE;
        const float* msk = (const float*)(sm + (st - sbase) + 4 * KV_TILE);

        float sc[8][4];
#pragma unroll
        for (int nt = 0; nt < 8; nt++)
#pragma unroll
            for (int c = 0; c < 4; c++) sc[nt][c] = 0.0f;

#pragma unroll
        for (int ks = 0; ks < 4; ks++) {
#pragma unroll
            for (int jp = 0; jp < 4; jp++) {
                uint32_t br = st + (uint32_t)(jp * 16 + ((l >> 4) * 8) + (l & 7)) * 144u
                            + ks * 32u + ((l >> 3) & 1) * 16u;
                uint32_t kh[4], kl[4];
                LDSM4(kh, br);
                LDSM4(kl, br + KV_TILE);
                mma16816(sc[2 * jp],     qh[ks], kh[0], kh[1]);
                mma16816(sc[2 * jp],     qh[ks], kl[0], kl[1]);
                mma16816(sc[2 * jp],     ql[ks], kh[0], kh[1]);
                mma16816(sc[2 * jp + 1], qh[ks], kh[2], kh[3]);
                mma16816(sc[2 * jp + 1], qh[ks], kl[2], kl[3]);
                mma16816(sc[2 * jp + 1], ql[ks], kh[2], kh[3]);
            }
        }

        float mx0 = -1e30f, mx1 = -1e30f;
#pragma unroll
        for (int nt = 0; nt < 8; nt++) {
            int col = nt * 8 + (l & 3) * 2;
            float k0m = msk[col] * (-1e9f), k1m = msk[col + 1] * (-1e9f);
            sc[nt][0] = fmaf(sc[nt][0], 0.125f, k0m);
            sc[nt][1] = fmaf(sc[nt][1], 0.125f, k1m);
            sc[nt][2] = fmaf(sc[nt][2], 0.125f, k0m);
            sc[nt][3] = fmaf(sc[nt][3], 0.125f, k1m);
            mx0 = fmaxf(mx0, fmaxf(sc[nt][0], sc[nt][1]));
            mx1 = fmaxf(mx1, fmaxf(sc[nt][2], sc[nt][3]));
        }
        mx0 = fmaxf(mx0, __shfl_xor_sync(0xffffffffu, mx0, 1));
        mx0 = fmaxf(mx0, __shfl_xor_sync(0xffffffffu, mx0, 2));
        mx1 = fmaxf(mx1, __shfl_xor_sync(0xffffffffu, mx1, 1));
        mx1 = fmaxf(mx1, __shfl_xor_sync(0xffffffffu, mx1, 2));

        float nm0 = fmaxf(m0, mx0), nm1 = fmaxf(m1, mx1);
        float al0 = __expf(m0 - nm0), al1 = __expf(m1 - nm1);
        m0 = nm0; m1 = nm1;

        float rs0 = 0.0f, rs1 = 0.0f;
#pragma unroll
        for (int nt = 0; nt < 8; nt++) {
            sc[nt][0] = __expf(sc[nt][0] - nm0);
            sc[nt][1] = __expf(sc[nt][1] - nm0);
            sc[nt][2] = __expf(sc[nt][2] - nm1);
            sc[nt][3] = __expf(sc[nt][3] - nm1);
            rs0 += sc[nt][0] + sc[nt][1];
            rs1 += sc[nt][2] + sc[nt][3];
        }
        rs0 += __shfl_xor_sync(0xffffffffu, rs0, 1);
        rs0 += __shfl_xor_sync(0xffffffffu, rs0, 2);
        rs1 += __shfl_xor_sync(0xffffffffu, rs1, 1);
        rs1 += __shfl_xor_sync(0xffffffffu, rs1, 2);
        l0 = l0 * al0 + rs0;
        l1 = l1 * al1 + rs1;
#pragma unroll
        for (int nt = 0; nt < 8; nt++) {
            o[nt][0] *= al0; o[nt][1] *= al0;
            o[nt][2] *= al1; o[nt][3] *= al1;
        }

#pragma unroll
        for (int j = 0; j < 4; j++) {
            uint32_t ph[4], pl[4];
            split2(sc[2 * j][0],     sc[2 * j][1],     ph[0], pl[0]);
            split2(sc[2 * j][2],     sc[2 * j][3],     ph[1], pl[1]);
            split2(sc[2 * j + 1][0], sc[2 * j + 1][1], ph[2], pl[2]);
            split2(sc[2 * j + 1][2], sc[2 * j + 1][3], ph[3], pl[3]);
#pragma unroll
            for (int np = 0; np < 4; np++) {
                uint32_t vr = st + 2 * KV_TILE
                            + (uint32_t)(j * 16 + ((l >> 3) & 1) * 8 + (l & 7)) * 144u
                            + (np * 16 + (l >> 4) * 8) * 2u;
                uint32_t vh[4], vl[4];
                LDSM4T(vh, vr);
                LDSM4T(vl, vr + KV_TILE);
                mma16816(o[2 * np],     ph, vh[0], vh[1]);
                mma16816(o[2 * np],     ph, vl[0], vl[1]);
                mma16816(o[2 * np],     pl, vh[0], vh[1]);
                mma16816(o[2 * np + 1], ph, vh[2], vh[3]);
                mma16816(o[2 * np + 1], ph, vl[2], vl[3]);
                mma16816(o[2 * np + 1], pl, vh[2], vh[3]);
            }
        }
    }

    float inv0 = 1.0f / l0, inv1 = 1.0f / l1;
#pragma unroll
    for (int nt = 0; nt < 8; nt++) {
        int col = h * DK + nt * 8 + (l & 3) * 2;
        size_t r0 = (size_t)(b * SEQ + q0 + w * 16 + (l >> 2)) * DMODEL + col;
        size_t r1 = r0 + 8 * DMODEL;
        uint32_t hi, lo;
        split2(o[nt][0] * inv0, o[nt][1] * inv0, hi, lo);
        *(uint32_t*)&Ohi[r0] = hi; *(uint32_t*)&Olo[r0] = lo;
        split2(o[nt][2] * inv1, o[nt][3] * inv1, hi, lo);
        *(uint32_t*)&Ohi[r1] = hi; *(uint32_t*)&Olo[r1] = lo;
    }
}

// ---------------------------------------------------------------------------
// prep kernels
// ---------------------------------------------------------------------------
// split x -> bf16 hi/lo; last block also concatenates the QKV bias
__global__ __launch_bounds__(256)
void split_f32_bias(const float* __restrict__ in, bf16* __restrict__ hi,
                    bf16* __restrict__ lo, int n4,
                    const float* __restrict__ bq, const float* __restrict__ bk,
                    const float* __restrict__ bv, float* __restrict__ bout)
{
    if ((int)blockIdx.x == gridDim.x - 1) {
        for (int j = threadIdx.x; j < NQKV; j += 256) {
            float v = (j < 768) ? bq[j] : (j < 1536) ? bk[j - 768] : bv[j - 1536];
            bout[j] = v;
        }
        return;
    }
    int i = blockIdx.x * 256 + threadIdx.x;
    if (i >= n4) return;
    float4 v = ((const float4*)in)[i];
    uint32_t h0, l0, h1, l1;
    split2(v.x, v.y, h0, l0);
    split2(v.z, v.w, h1, l1);
    *(uint32_t*)&hi[i * 4]     = h0;
    *(uint32_t*)&hi[i * 4 + 2] = h1;
    *(uint32_t*)&lo[i * 4]     = l0;
    *(uint32_t*)&lo[i * 4 + 2] = l1;
}

// W [K,N] f32 -> out[N][K] split bf16 (transpose)
__global__ __launch_bounds__(256)
void wtrans(const float* __restrict__ W, bf16* __restrict__ hi,
            bf16* __restrict__ lo, int K, int N)
{
    __shared__ float t[32][33];
    const int n0 = blockIdx.x * 32, k0 = blockIdx.y * 32;
    const int tx = threadIdx.x & 31, ty = threadIdx.x >> 5;
#pragma unroll
    for (int i = 0; i < 4; i++)
        t[ty + 8 * i][tx] = W[(size_t)(k0 + ty + 8 * i) * N + n0 + tx];
    __syncthreads();
#pragma unroll
    for (int i = 0; i < 4; i++) {
        float v = t[tx][ty + 8 * i];
        size_t off = (size_t)(n0 + ty + 8 * i) * K + k0 + tx;
        __nv_bfloat16 hb = __float2bfloat16(v);
        hi[off] = hb;
        lo[off] = __float2bfloat16(v - __bfloat162float(hb));
    }
}

// fused Wq/Wk/Wv transpose (z selects matrix)
__global__ __launch_bounds__(256)
void wtrans_qkv(const float* __restrict__ Wq, const float* __restrict__ Wk,
                const float* __restrict__ Wv, bf16* __restrict__ hi,
                bf16* __restrict__ lo)
{
    __shared__ float t[32][33];
    const int z = blockIdx.z;
    const float* W = (z == 0) ? Wq : (z == 1) ? Wk : Wv;
    bf16* ho = hi + (size_t)z * 768 * 768;
    bf16* loo = lo + (size_t)z * 768 * 768;
    const int n0 = blockIdx.x * 32, k0 = blockIdx.y * 32;
    const int tx = threadIdx.x & 31, ty = threadIdx.x >> 5;
#pragma unroll
    for (int i = 0; i < 4; i++)
        t[ty + 8 * i][tx] = W[(size_t)(k0 + ty + 8 * i) * 768 + n0 + tx];
    __syncthreads();
#pragma unroll
    for (int i = 0; i < 4; i++) {
        float v = t[tx][ty + 8 * i];
        size_t off = (size_t)(n0 + ty + 8 * i) * 768 + k0 + tx;
        __nv_bfloat16 hb = __float2bfloat16(v);
        ho[off] = hb;
        loo[off] = __float2bfloat16(v - __bfloat162float(hb));
    }
}

// ---------------------------------------------------------------------------
// LayerNorm (768)
// ---------------------------------------------------------------------------
template<int EMIT_SPLIT>
__global__ __launch_bounds__(256)
void layernorm_kernel(const float* __restrict__ X, const float* __restrict__ gamma,
                      const float* __restrict__ beta, float* __restrict__ Y,
                      bf16* __restrict__ Yhi, bf16* __restrict__ Ylo)
{
    const int row = blockIdx.x;
    const int tid = threadIdx.x;
    const float* x = X + (size_t)row * DMODEL;

    float v[3];
    float sum = 0.0f, sq = 0.0f;
#pragma unroll
    for (int i = 0; i < 3; i++) {
        v[i] = x[tid + i * 256];
        sum += v[i];
        sq = fmaf(v[i], v[i], sq);
    }
#pragma unroll
    for (int off = 16; off > 0; off >>= 1) {
        sum += __shfl_xor_sync(0xffffffffu, sum, off);
        sq  += __shfl_xor_sync(0xffffffffu, sq,  off);
    }
    __shared__ float rsm[8], rqm[8], bc[2];
    int w = tid >> 5, lane = tid & 31;
    if (lane == 0) { rsm[w] = sum; rqm[w] = sq; }
    __syncthreads();
    if (tid == 0) {
        float s = 0.0f, q = 0.0f;
#pragma unroll
        for (int i = 0; i < 8; i++) { s += rsm[i]; q += rqm[i]; }
        float mean = s * (1.0f / DMODEL);
        float var = q * (1.0f / DMODEL) - mean * mean;
        bc[0] = mean;
        bc[1] = rsqrtf(var + 1e-3f);
    }
    __syncthreads();
    float mean = bc[0], inv = bc[1];
#pragma unroll
    for (int i = 0; i < 3; i++) {
        int col = tid + i * 256;
        float y = (v[i] - mean) * inv * gamma[col] + beta[col];
        size_t off = (size_t)row * DMODEL + col;
        Y[off] = y;
        if (EMIT_SPLIT) {
            __nv_bfloat16 hb = __float2bfloat16(y);
            Yhi[off] = hb;
            Ylo[off] = __float2bfloat16(y - __bfloat162float(hb));
        }
    }
}

// ---------------------------------------------------------------------------
// launch
// ---------------------------------------------------------------------------
#define SMEM_NI8 (3 * (20480 + 2 * 2560 * 8))   // 184320
#define SMEM_NI4 (3 * (20480 + 2 * 2560 * 4))   // 122880

extern "C" void kernel_launch(void* const* d_in, const int* in_sizes, int n_in,
                              void* d_out, int out_size)
{
    const float* x    = (const float*)d_in[0];
    const float* mask = (const float*)d_in[1];
    const float* Wq   = (const float*)d_in[2];
    const float* bq   = (const float*)d_in[3];
    const float* Wk   = (const float*)d_in[4];
    const float* bk   = (const float*)d_in[5];
    const float* Wv   = (const float*)d_in[6];
    const float* bv   = (const float*)d_in[7];
    const float* Wo   = (const float*)d_in[8];
    const float* bo   = (const float*)d_in[9];
    const float* W1   = (const float*)d_in[10];
    const float* b1   = (const float*)d_in[11];
    const float* W2   = (const float*)d_in[12];
    const float* b2   = (const float*)d_in[13];
    const float* g1   = (const float*)d_in[14];
    const float* be1  = (const float*)d_in[15];
    const float* g2   = (const float*)d_in[16];
    const float* be2  = (const float*)d_in[17];

    float *pRes, *pX1, *pBqkv;
    bf16 *pQKVhi, *pQKVlo, *pAhi, *pAlo, *pHhi, *pHlo, *pWhi, *pWlo;
    cudaGetSymbolAddress((void**)&pQKVhi, g_QKVhi);
    cudaGetSymbolAddress((void**)&pQKVlo, g_QKVlo);
    cudaGetSymbolAddress((void**)&pAhi,   g_Ahi);
    cudaGetSymbolAddress((void**)&pAlo,   g_Alo);
    cudaGetSymbolAddress((void**)&pHhi,   g_Hhi);
    cudaGetSymbolAddress((void**)&pHlo,   g_Hlo);
    cudaGetSymbolAddress((void**)&pWhi,   g_Whi);
    cudaGetSymbolAddress((void**)&pWlo,   g_Wlo);
    cudaGetSymbolAddress((void**)&pRes,   g_res);
    cudaGetSymbolAddress((void**)&pX1,    g_x1);
    cudaGetSymbolAddress((void**)&pBqkv,  g_bqkv);

    static bool attr_set = false;
    if (!attr_set) {
        cudaFuncSetAttribute(gemm_mma<8, 0, 0, 1>, cudaFuncAttributeMaxDynamicSharedMemorySize, SMEM_NI8);
        cudaFuncSetAttribute(gemm_mma<8, 1, 0, 1>, cudaFuncAttributeMaxDynamicSharedMemorySize, SMEM_NI8);
        cudaFuncSetAttribute(gemm_mma<4, 0, 1, 0>, cudaFuncAttributeMaxDynamicSharedMemorySize, SMEM_NI4);
        cudaFuncSetAttribute(attention_mma, cudaFuncAttributeMaxDynamicSharedMemorySize, ATT_SMEM);
        attr_set = true;
    }

    dim3 blk(256);

    // launches 0-4: prep (exactly 5, so ncu -s 5 profiles the QKV GEMM)
    wtrans_qkv<<<dim3(24, 24, 3), blk>>>(Wq, Wk, Wv, pWhi + OFF_WQKV, pWlo + OFF_WQKV);
    wtrans<<<dim3(24, 24), blk>>>(Wo, pWhi + OFF_WO, pWlo + OFF_WO, 768, 768);
    wtrans<<<dim3(64, 24), blk>>>(W1, pWhi + OFF_W1, pWlo + OFF_W1, 768, DFF);
    wtrans<<<dim3(24, 64), blk>>>(W2, pWhi + OFF_W2, pWlo + OFF_W2, DFF, 768);
    {
        int n4 = MDIM * DMODEL / 4;
        split_f32_bias<<<(n4 + 255) / 256 + 1, blk>>>(x, pAhi, pAlo, n4, bq, bk, bv, pBqkv);
    }

    // launch 5: fused QKV  [8192,768]@[768,2304], CTA 128x256
    gemm_mma<8, 0, 0, 1><<<dim3(NQKV / 256, MDIM / 128), blk, SMEM_NI8>>>(
        pAhi, pAlo, pWhi + OFF_WQKV, pWlo + OFF_WQKV, pBqkv, nullptr,
        nullptr, pQKVhi, pQKVlo, MDIM, NQKV, DMODEL);

    // launch 6: attention
    attention_mma<<<dim3(SEQ / 128, BATCH * NHEAD), blk, ATT_SMEM>>>(
        pQKVhi, pQKVlo, mask, pAhi, pAlo);

    // launch 7: O projection + residual(x), CTA 128x128
    gemm_mma<4, 0, 1, 0><<<dim3(DMODEL / 128, MDIM / 128), blk, SMEM_NI4>>>(
        pAhi, pAlo, pWhi + OFF_WO, pWlo + OFF_WO, bo, x,
        pRes, nullptr, nullptr, MDIM, DMODEL, DMODEL);

    // launch 8: LN1
    layernorm_kernel<1><<<MDIM, blk>>>(pRes, g1, be1, pX1, pAhi, pAlo);

    // launch 9: FFN1 relu(x1@W1+b1), CTA 128x256
    gemm_mma<8, 1, 0, 1><<<dim3(DFF / 256, MDIM / 128), blk, SMEM_NI8>>>(
        pAhi, pAlo, pWhi + OFF_W1, pWlo + OFF_W1, b1, nullptr,
        nullptr, pHhi, pHlo, MDIM, DFF, DMODEL);

    // launch 10: FFN2 H@W2+b2+x1, CTA 128x128
    gemm_mma<4, 0, 1, 0><<<dim3(DMODEL / 128, MDIM / 128), blk, SMEM_NI4>>>(
        pHhi, pHlo, pWhi + OFF_W2, pWlo + OFF_W2, b2, pX1,
        pRes, nullptr, nullptr, MDIM, DMODEL, DFF);

    // launch 11: LN2
    layernorm_kernel<0><<<MDIM, blk>>>(pRes, g2, be2, (float*)d_out, nullptr, nullptr);
}